// round 3
// baseline (speedup 1.0000x reference)
#include <cuda_runtime.h>
#include <math.h>

#define NB 128
#define HH 1024
#define DD 1024
#define TT 256
#define G4 4096
#define KS 4          // K slices per step GEMM
#define KSL 256       // K per slice

// Scratch (__device__ globals: allocation-free rule)
__device__ float g_WsumT[(size_t)HH * G4];   // (Wih+Whh)^T, k-major [k][gatecol]
__device__ float g_WihT [(size_t)HH * G4];   // Wih^T, k-major
__device__ float g_WfcT [(size_t)HH * DD];   // Wfc^T, k-major [k][d]
__device__ float g_bsum [G4];                // bih + bhh
__device__ float g_c    [NB * HH];           // cell state
__device__ float g_part [(size_t)KS * NB * G4];      // K-slice partial gates
__device__ float g_hs   [(size_t)TT * NB * HH];      // hidden states [t][n][h]

// ---------------------------------------------------------------------------
__global__ void prep_kernel(const float* __restrict__ Wih,
                            const float* __restrict__ Whh,
                            const float* __restrict__ bih,
                            const float* __restrict__ bhh,
                            const float* __restrict__ Wfc)
{
    size_t idx = (size_t)blockIdx.x * blockDim.x + threadIdx.x;
    size_t stride = (size_t)gridDim.x * blockDim.x;

    for (size_t i = idx; i < (size_t)HH * G4; i += stride) {
        int k   = (int)(i >> 12);
        int col = (int)(i & 4095);
        float a = Wih[(size_t)col * HH + k];
        float b = Whh[(size_t)col * HH + k];
        g_WihT[i]  = a;
        g_WsumT[i] = a + b;
    }
    for (size_t i = idx; i < (size_t)HH * DD; i += stride) {
        int k   = (int)(i >> 10);
        int col = (int)(i & 1023);
        g_WfcT[i] = Wfc[(size_t)col * HH + k];
    }
    for (size_t i = idx; i < (size_t)G4; i += stride)
        g_bsum[i] = bih[i] + bhh[i];
}

// ---------------------------------------------------------------------------
// Packed f32x2 helpers
// ---------------------------------------------------------------------------
__device__ __forceinline__ unsigned long long pack2(float x, float y) {
    unsigned long long r;
    asm("mov.b64 %0, {%1, %2};" : "=l"(r) : "f"(x), "f"(y));
    return r;
}
__device__ __forceinline__ void unpack2(unsigned long long v, float& x, float& y) {
    asm("mov.b64 {%0, %1}, %2;" : "=f"(x), "=f"(y) : "l"(v));
}
__device__ __forceinline__ void ffma2(unsigned long long& acc,
                                      unsigned long long a, unsigned long long b) {
    asm("fma.rn.f32x2 %0, %1, %2, %0;" : "+l"(acc) : "l"(a), "l"(b));
}

#define BK 64
#define AS_STRIDE 34

// ---------------------------------------------------------------------------
// GEMM micro-kernel body shared by lstm_gemm and fc.
// CTA: 256 threads, tile 32 rows x 128 cols, micro-tile 8m x 2col.
//   gcp = tid&63 (col pair), mg = tid>>6 (8-row group)
// A staged k-major in SMEM (broadcast LDS.64); W streamed as LDG.64 (L2-hit).
// ---------------------------------------------------------------------------
struct Acc16 { unsigned long long a0[4]; unsigned long long a1[4]; };

__device__ __forceinline__ void gemm_tile(const float* __restrict__ x,  // [rows][K] at row m0
                                          const float* __restrict__ WT, // [K][ldw] col base included
                                          int ldw, int kcount,
                                          float* As, int tid, int gcp, int mg,
                                          Acc16& acc)
{
#pragma unroll
    for (int i = 0; i < 4; i++) { acc.a0[i] = 0ULL; acc.a1[i] = 0ULL; }

    for (int kb = 0; kb < kcount; kb += BK) {
#pragma unroll
        for (int j = 0; j < 2; j++) {
            int idx = tid + j * 256;          // 512 float4
            int m   = idx >> 4;               // 0..31
            int kq  = idx & 15;
            float4 v = *reinterpret_cast<const float4*>(x + (size_t)m * HH + kb + kq * 4);
            As[(kq * 4 + 0) * AS_STRIDE + m] = v.x;
            As[(kq * 4 + 1) * AS_STRIDE + m] = v.y;
            As[(kq * 4 + 2) * AS_STRIDE + m] = v.z;
            As[(kq * 4 + 3) * AS_STRIDE + m] = v.w;
        }
        __syncthreads();

        const float* Wp = WT + (size_t)kb * ldw + 2 * gcp;
#pragma unroll 8
        for (int k = 0; k < BK; k++) {
            float2 w = *reinterpret_cast<const float2*>(Wp + (size_t)k * ldw);
            unsigned long long wp0 = pack2(w.x, w.x);
            unsigned long long wp1 = pack2(w.y, w.y);
            const float* arow = &As[k * AS_STRIDE + mg * 8];
#pragma unroll
            for (int mp = 0; mp < 4; mp++) {
                unsigned long long a2 =
                    *reinterpret_cast<const unsigned long long*>(arow + 2 * mp);
                ffma2(acc.a0[mp], a2, wp0);
                ffma2(acc.a1[mp], a2, wp1);
            }
        }
        __syncthreads();
    }
}

// ---------------------------------------------------------------------------
// Per-step gate GEMM, K-split. grid (32 gc-tiles, 4 m-tiles, 4 k-slices).
// Writes partial gates to g_part[ks].
// ---------------------------------------------------------------------------
__global__ void __launch_bounds__(256) lstm_gemm(const float* __restrict__ hT, int t)
{
    __shared__ float As[BK * AS_STRIDE];

    int tid = threadIdx.x;
    int gcp = tid & 63;
    int mg  = tid >> 6;
    int gcbase = blockIdx.x * 128;
    int m0     = blockIdx.y * 32;
    int ks     = blockIdx.z;

    const float* x  = ((t == 0) ? hT : (g_hs + (size_t)(t - 1) * (NB * HH)))
                      + (size_t)m0 * HH + ks * KSL;
    const float* WT = ((t == 0) ? g_WihT : g_WsumT)
                      + (size_t)ks * KSL * G4 + gcbase;

    Acc16 acc;
    gemm_tile(x, WT, G4, KSL, As, tid, gcp, mg, acc);

    // store partials: rows m0+mg*8+2mp(+1), cols gcbase+2gcp(+1) as float2
    float* out = g_part + ((size_t)ks * NB + m0 + mg * 8) * G4 + gcbase + 2 * gcp;
#pragma unroll
    for (int mp = 0; mp < 4; mp++) {
        float x0, x1, y0, y1;
        unpack2(acc.a0[mp], x0, x1);
        unpack2(acc.a1[mp], y0, y1);
        *reinterpret_cast<float2*>(out + (size_t)(2 * mp)     * G4) = make_float2(x0, y0);
        *reinterpret_cast<float2*>(out + (size_t)(2 * mp + 1) * G4) = make_float2(x1, y1);
    }
}

// ---------------------------------------------------------------------------
// Pointwise: sum K-slice partials + bias, activations, c/h update.
// 32768 float4 cells. grid 128 x 256 threads.
// ---------------------------------------------------------------------------
__device__ __forceinline__ float4 sig4(float4 v) {
    v.x = 1.0f / (1.0f + expf(-v.x));
    v.y = 1.0f / (1.0f + expf(-v.y));
    v.z = 1.0f / (1.0f + expf(-v.z));
    v.w = 1.0f / (1.0f + expf(-v.w));
    return v;
}
__device__ __forceinline__ float4 tanh4(float4 v) {
    v.x = tanhf(v.x); v.y = tanhf(v.y); v.z = tanhf(v.z); v.w = tanhf(v.w);
    return v;
}
__device__ __forceinline__ float4 add4(float4 a, float4 b) {
    return make_float4(a.x + b.x, a.y + b.y, a.z + b.z, a.w + b.w);
}

__global__ void __launch_bounds__(256) lstm_pointwise(int t)
{
    int idx = blockIdx.x * 256 + threadIdx.x;   // 0..32767
    int m = idx >> 8;
    int j = (idx & 255) * 4;

    float4 gate[4];
#pragma unroll
    for (int g = 0; g < 4; g++) {
        size_t off = (size_t)m * G4 + g * HH + j;
        float4 s = *reinterpret_cast<const float4*>(g_part + off);
#pragma unroll
        for (int ks = 1; ks < KS; ks++)
            s = add4(s, *reinterpret_cast<const float4*>(g_part + (size_t)ks * NB * G4 + off));
        gate[g] = add4(s, *reinterpret_cast<const float4*>(g_bsum + g * HH + j));
    }

    float4 iv = sig4(gate[0]);
    float4 fv = sig4(gate[1]);
    float4 gv = tanh4(gate[2]);
    float4 ov = sig4(gate[3]);

    size_t ci = (size_t)m * HH + j;
    float4 cp = (t == 0) ? make_float4(0.f, 0.f, 0.f, 0.f)
                         : *reinterpret_cast<const float4*>(g_c + ci);
    float4 cn = make_float4(fv.x * cp.x + iv.x * gv.x,
                            fv.y * cp.y + iv.y * gv.y,
                            fv.z * cp.z + iv.z * gv.z,
                            fv.w * cp.w + iv.w * gv.w);
    *reinterpret_cast<float4*>(g_c + ci) = cn;

    float4 tc = tanh4(cn);
    float4 hn = make_float4(ov.x * tc.x, ov.y * tc.y, ov.z * tc.z, ov.w * tc.w);
    *reinterpret_cast<float4*>(g_hs + (size_t)t * (NB * HH) + ci) = hn;
}

// ---------------------------------------------------------------------------
// Final FC: out[n][t][d] = hs[t][n][:] @ WfcT + b_fc.
// Rows r = t*128 + n (32768). grid (8 d-tiles, 1024 r-tiles).
// ---------------------------------------------------------------------------
__global__ void __launch_bounds__(256) fc_kernel(const float* __restrict__ bfc,
                                                 float* __restrict__ out)
{
    __shared__ float As[BK * AS_STRIDE];

    int tid = threadIdx.x;
    int gcp = tid & 63;
    int mg  = tid >> 6;
    int dbase = blockIdx.x * 128;
    int r0    = blockIdx.y * 32;

    const float* x  = g_hs + (size_t)r0 * HH;
    const float* WT = g_WfcT + dbase;

    Acc16 acc;
    gemm_tile(x, WT, DD, HH, As, tid, gcp, mg, acc);

    int d = dbase + 2 * gcp;
    float b0 = bfc[d], b1 = bfc[d + 1];
#pragma unroll
    for (int mp = 0; mp < 4; mp++) {
        float x0, x1, y0, y1;
        unpack2(acc.a0[mp], x0, x1);
        unpack2(acc.a1[mp], y0, y1);
        int r = r0 + mg * 8 + 2 * mp;
        *reinterpret_cast<float2*>(out + ((size_t)(r & 127) * TT + (r >> 7)) * DD + d)
            = make_float2(x0 + b0, y0 + b1);
        r += 1;
        *reinterpret_cast<float2*>(out + ((size_t)(r & 127) * TT + (r >> 7)) * DD + d)
            = make_float2(x1 + b0, y1 + b1);
    }
}

// ---------------------------------------------------------------------------
extern "C" void kernel_launch(void* const* d_in, const int* in_sizes, int n_in,
                              void* d_out, int out_size)
{
    const float* hT  = (const float*)d_in[0];
    const float* Wih = (const float*)d_in[1];
    const float* Whh = (const float*)d_in[2];
    const float* bih = (const float*)d_in[3];
    const float* bhh = (const float*)d_in[4];
    const float* Wfc = (const float*)d_in[5];
    const float* bfc = (const float*)d_in[6];
    float* out = (float*)d_out;

    prep_kernel<<<2048, 256>>>(Wih, Whh, bih, bhh, Wfc);

    dim3 ggrid(G4 / 128, NB / 32, KS);      // (32, 4, 4) = 512 CTAs
    for (int t = 0; t < TT; t++) {
        lstm_gemm<<<ggrid, 256>>>(hT, t);
        lstm_pointwise<<<128, 256>>>(t);
    }

    dim3 fgrid(DD / 128, (TT * NB) / 32);   // (8, 1024)
    fc_kernel<<<fgrid, 256>>>(bfc, out);
}

// round 5
// speedup vs baseline: 3.4857x; 3.4857x over previous
#include <cuda_runtime.h>
#include <cuda_bf16.h>
#include <cstdint>

#define TT 256
#define NCTA 128
#define ACHP 18432                 // padded A chunk: 128 rows x 144B
#define SLOTP (16*ACHP)            // 294912 per A slot per matrix
#define BCHP 4608                  // padded W chunk: 32 rows x 144B
#define WCTAP (16*BCHP)            // 73728 per CTA per matrix
#define FCDP (16*ACHP)             // FC W d-tile: 16 chunks x (128 rows x 144B)

// ------------------------- device scratch -------------------------
__device__ __align__(128) unsigned char g_Ahi[(size_t)(TT+1)*SLOTP];
__device__ __align__(128) unsigned char g_Alo[(size_t)(TT+1)*SLOTP];
__device__ __align__(128) unsigned char g_WsHi[(size_t)NCTA*WCTAP];
__device__ __align__(128) unsigned char g_WsLo[(size_t)NCTA*WCTAP];
__device__ __align__(128) unsigned char g_W0Hi[(size_t)NCTA*WCTAP];
__device__ __align__(128) unsigned char g_W0Lo[(size_t)NCTA*WCTAP];
__device__ __align__(128) unsigned char g_FcHi[(size_t)8*FCDP];
__device__ __align__(128) unsigned char g_FcLo[(size_t)8*FCDP];
__device__ float g_biasP[NCTA*32];
__device__ unsigned g_bar;

// ------------------------- helpers -------------------------
__device__ __forceinline__ uint32_t smem_u32(const void* p) {
    uint32_t a;
    asm("{ .reg .u64 t; cvta.to.shared.u64 t, %1; cvt.u32.u64 %0, t; }" : "=r"(a) : "l"(p));
    return a;
}
__device__ __forceinline__ void cpa16(uint32_t dst, const void* src) {
    asm volatile("cp.async.cg.shared.global [%0], [%1], 16;" :: "r"(dst), "l"(src));
}
#define CP_COMMIT() asm volatile("cp.async.commit_group;")
#define CP_WAIT1()  asm volatile("cp.async.wait_group 1;")
#define CP_WAIT0()  asm volatile("cp.async.wait_group 0;")

__device__ __forceinline__ void hmma(float* c, const uint32_t* a, uint32_t b0, uint32_t b1) {
    asm volatile(
        "mma.sync.aligned.m16n8k16.row.col.f32.bf16.bf16.f32 "
        "{%0,%1,%2,%3}, {%4,%5,%6,%7}, {%8,%9}, {%0,%1,%2,%3};"
        : "+f"(c[0]), "+f"(c[1]), "+f"(c[2]), "+f"(c[3])
        : "r"(a[0]), "r"(a[1]), "r"(a[2]), "r"(a[3]), "r"(b0), "r"(b1));
}
__device__ __forceinline__ float sigf(float x)  { return 1.0f / (1.0f + __expf(-x)); }
__device__ __forceinline__ float tanhx(float x) { return 2.0f / (1.0f + __expf(-2.0f * x)) - 1.0f; }

// pack 8 floats -> bf16 hi uint4 + bf16 lo uint4
__device__ __forceinline__ void pack8(const float* v, uint4& hi, uint4& lo) {
    __nv_bfloat16 h[8]; float r[8];
#pragma unroll
    for (int e = 0; e < 8; e++) { h[e] = __float2bfloat16(v[e]); r[e] = v[e] - __bfloat162float(h[e]); }
    uint32_t* hw = (uint32_t*)&hi; uint32_t* lw = (uint32_t*)&lo;
#pragma unroll
    for (int q = 0; q < 4; q++) {
        __nv_bfloat162 ph = __halves2bfloat162(h[2*q], h[2*q+1]);
        __nv_bfloat162 pl = __halves2bfloat162(__float2bfloat16(r[2*q]), __float2bfloat16(r[2*q+1]));
        hw[q] = *(uint32_t*)&ph; lw[q] = *(uint32_t*)&pl;
    }
}

// ------------------------- prep -------------------------
__global__ void prep(const float* __restrict__ hT, const float* __restrict__ Wih,
                     const float* __restrict__ Whh, const float* __restrict__ bih,
                     const float* __restrict__ bhh, const float* __restrict__ Wfc)
{
    size_t idx = (size_t)blockIdx.x * blockDim.x + threadIdx.x;
    size_t str = (size_t)gridDim.x * blockDim.x;
    if (idx == 0) g_bar = 0;

    // step weights: cta(128) x np(32) x kgroup(128 of 8)
    for (size_t i = idx; i < (size_t)524288; i += str) {
        int kg = (int)(i & 127), np = (int)((i >> 7) & 31), cta = (int)(i >> 12);
        int row = (np & 3) * 1024 + cta * 8 + (np >> 2);
        int k = kg * 8;
        float wi[8], ws[8];
#pragma unroll
        for (int e = 0; e < 8; e++) {
            float a = Wih[(size_t)row * 1024 + k + e];
            wi[e] = a; ws[e] = a + Whh[(size_t)row * 1024 + k + e];
        }
        size_t base = (size_t)cta * WCTAP + (size_t)(kg >> 3) * BCHP + np * 144 + (kg & 7) * 16;
        uint4 h4, l4;
        pack8(wi, h4, l4);
        *(uint4*)(g_W0Hi + base) = h4; *(uint4*)(g_W0Lo + base) = l4;
        pack8(ws, h4, l4);
        *(uint4*)(g_WsHi + base) = h4; *(uint4*)(g_WsLo + base) = l4;
    }
    // fc weights: dt(8) x np(128) x kgroup(128)
    for (size_t i = idx; i < (size_t)131072; i += str) {
        int kg = (int)(i & 127), np = (int)((i >> 7) & 127), dt = (int)(i >> 14);
        float w[8];
#pragma unroll
        for (int e = 0; e < 8; e++) w[e] = Wfc[(size_t)(dt * 128 + np) * 1024 + kg * 8 + e];
        size_t base = (size_t)dt * FCDP + (size_t)(kg >> 3) * ACHP + np * 144 + (kg & 7) * 16;
        uint4 h4, l4;
        pack8(w, h4, l4);
        *(uint4*)(g_FcHi + base) = h4; *(uint4*)(g_FcLo + base) = l4;
    }
    // hT -> slot 0: m(128) x kgroup(128)
    for (size_t i = idx; i < (size_t)16384; i += str) {
        int kg = (int)(i & 127), m = (int)(i >> 7);
        float v[8];
#pragma unroll
        for (int e = 0; e < 8; e++) v[e] = hT[(size_t)m * 1024 + kg * 8 + e];
        size_t base = (size_t)(kg >> 3) * ACHP + m * 144 + (kg & 7) * 16;
        uint4 h4, l4;
        pack8(v, h4, l4);
        *(uint4*)(g_Ahi + base) = h4; *(uint4*)(g_Alo + base) = l4;
    }
    // bias (permuted, i=+0 f=+1 g=+2 o=+3 per unit)
    for (size_t i = idx; i < (size_t)4096; i += str) {
        int np = (int)(i & 31), cta = (int)(i >> 5);
        int row = (np & 3) * 1024 + cta * 8 + (np >> 2);
        g_biasP[i] = bih[row] + bhh[row];
    }
}

// ------------------------- persistent LSTM -------------------------
// smem: 2 buffers x 46080 { Ahi 18432 | Alo 18432 | Bhi 4608 | Blo 4608 }, bias at 92160
#define BUFSZ 46080
#define SM_STEP (2*BUFSZ + 128)

__global__ void __launch_bounds__(256, 1) lstm_persistent()
{
    extern __shared__ unsigned char smem[];
    const uint32_t sb = smem_u32(smem);
    const int tid = threadIdx.x;
    const int w = tid >> 5, lane = tid & 31;
    const int g = lane >> 2, tig = lane & 3;
    const int cta = blockIdx.x;

    if (tid < 32) ((float*)(smem + 2 * BUFSZ))[tid] = g_biasP[cta * 32 + tid];
    const float* biasS = (const float*)(smem + 2 * BUFSZ);

    float c[4] = {0.f, 0.f, 0.f, 0.f};

    for (int t = 0; t < TT; t++) {
        // global step barrier
        if (tid == 0 && t > 0) {
            unsigned tgt = (unsigned)(NCTA * t), v;
            do {
                asm volatile("ld.acquire.gpu.global.u32 %0, [%1];" : "=r"(v) : "l"(&g_bar));
                if ((int)(v - tgt) >= 0) break;
                __nanosleep(32);
            } while (1);
        }
        __syncthreads();

        const unsigned char* aH = g_Ahi + (size_t)t * SLOTP;
        const unsigned char* aL = g_Alo + (size_t)t * SLOTP;
        const unsigned char* bH = (t ? g_WsHi : g_W0Hi) + (size_t)cta * WCTAP;
        const unsigned char* bL = (t ? g_WsLo : g_W0Lo) + (size_t)cta * WCTAP;

        auto issue = [&](int kc) {
            uint32_t d = sb + (kc & 1) * BUFSZ;
            const unsigned char* sA = aH + (size_t)kc * ACHP;
            const unsigned char* sL = aL + (size_t)kc * ACHP;
            const unsigned char* sB = bH + (size_t)kc * BCHP;
            const unsigned char* sC = bL + (size_t)kc * BCHP;
            for (int i = tid; i < 1152; i += 256) cpa16(d + i * 16, sA + i * 16);
            for (int i = tid; i < 1152; i += 256) cpa16(d + 18432 + i * 16, sL + i * 16);
            for (int i = tid; i < 288; i += 256) cpa16(d + 36864 + i * 16, sB + i * 16);
            for (int i = tid; i < 288; i += 256) cpa16(d + 41472 + i * 16, sC + i * 16);
            CP_COMMIT();
        };

        float acc[4][4];
#pragma unroll
        for (int n = 0; n < 4; n++)
#pragma unroll
            for (int q = 0; q < 4; q++) acc[n][q] = 0.f;

        issue(0); issue(1);
        for (int kc = 0; kc < 16; kc++) {
            if (kc == 15) CP_WAIT0(); else CP_WAIT1();
            __syncthreads();
            const unsigned char* As = smem + (kc & 1) * BUFSZ;
            const unsigned char* Al = As + 18432;
            const unsigned char* Bh = As + 36864;
            const unsigned char* Bl = As + 41472;
            const int rb = (16 * w + g) * 144 + tig * 4;
#pragma unroll
            for (int ks = 0; ks < 4; ks++) {
                const int ao = rb + ks * 32;
                uint32_t ah[4], al4[4];
                ah[0] = *(const uint32_t*)(As + ao);
                ah[1] = *(const uint32_t*)(As + ao + 1152);
                ah[2] = *(const uint32_t*)(As + ao + 16);
                ah[3] = *(const uint32_t*)(As + ao + 1168);
                al4[0] = *(const uint32_t*)(Al + ao);
                al4[1] = *(const uint32_t*)(Al + ao + 1152);
                al4[2] = *(const uint32_t*)(Al + ao + 16);
                al4[3] = *(const uint32_t*)(Al + ao + 1168);
#pragma unroll
                for (int nt = 0; nt < 4; nt++) {
                    const int bo = (8 * nt + g) * 144 + tig * 4 + ks * 32;
                    uint32_t bh0 = *(const uint32_t*)(Bh + bo);
                    uint32_t bh1 = *(const uint32_t*)(Bh + bo + 16);
                    uint32_t bl0 = *(const uint32_t*)(Bl + bo);
                    uint32_t bl1 = *(const uint32_t*)(Bl + bo + 16);
                    hmma(acc[nt], ah, bh0, bh1);
                    hmma(acc[nt], al4, bh0, bh1);
                    hmma(acc[nt], ah, bl0, bl1);
                }
            }
            __syncthreads();
            if (kc + 2 < 16) issue(kc + 2);
        }

        // epilogue: pair (i,f)/(g,o) lanes, activations, c/h update, split-store h
        const int parity = lane & 1;
#pragma unroll
        for (int nt = 0; nt < 4; nt++) {
            float d0 = acc[nt][0], d1 = acc[nt][1], d2 = acc[nt][2], d3 = acc[nt][3];
            float s0 = parity ? d0 : d2;
            float s1 = parity ? d1 : d3;
            float r0 = __shfl_xor_sync(0xffffffffu, s0, 1);
            float r1 = __shfl_xor_sync(0xffffffffu, s1, 1);
            float ivr, fvr, gvr, ovr; int m;
            if (!parity) { ivr = d0; fvr = d1; gvr = r0; ovr = r1; m = 16 * w + g; }
            else         { ivr = r0; fvr = r1; gvr = d2; ovr = d3; m = 16 * w + g + 8; }
            int u = 2 * nt + (tig >> 1);
            const float* bb = biasS + 4 * u;
            float iv = sigf(ivr + bb[0]);
            float fv = sigf(fvr + bb[1]);
            float gv = tanhx(gvr + bb[2]);
            float ov = sigf(ovr + bb[3]);
            c[nt] = fv * c[nt] + iv * gv;
            float h = ov * tanhx(c[nt]);
            int j = cta * 8 + u;
            size_t off = (size_t)(t + 1) * SLOTP + (size_t)(j >> 6) * ACHP
                       + (size_t)m * 144 + (j & 63) * 2;
            __nv_bfloat16 hh = __float2bfloat16(h);
            *(__nv_bfloat16*)(g_Ahi + off) = hh;
            *(__nv_bfloat16*)(g_Alo + off) = __float2bfloat16(h - __bfloat162float(hh));
        }
        __syncthreads();
        if (tid == 0)
            asm volatile("red.release.gpu.global.add.u32 [%0], %1;" :: "l"(&g_bar), "r"(1u) : "memory");
    }
}

// ------------------------- FC -------------------------
// smem: 2 buffers x 73728 { Ahi 18432 | Alo 18432 | Bhi 18432 | Blo 18432 }
#define FBUFSZ 73728
#define SM_FC (2*FBUFSZ)

__global__ void __launch_bounds__(256, 1) fc_kernel(const float* __restrict__ bfc,
                                                    float* __restrict__ out)
{
    extern __shared__ unsigned char smem[];
    const uint32_t sb = smem_u32(smem);
    const int tid = threadIdx.x;
    const int w = tid >> 5, lane = tid & 31;
    const int g = lane >> 2, tig = lane & 3;
    const int s = blockIdx.x;   // time step t = s, data in slot s+1
    const int dt = blockIdx.y;  // d tile of 128

    const unsigned char* aH = g_Ahi + (size_t)(s + 1) * SLOTP;
    const unsigned char* aL = g_Alo + (size_t)(s + 1) * SLOTP;
    const unsigned char* bH = g_FcHi + (size_t)dt * FCDP;
    const unsigned char* bL = g_FcLo + (size_t)dt * FCDP;

    auto issue = [&](int kc) {
        uint32_t d = sb + (kc & 1) * FBUFSZ;
        const unsigned char* s0 = aH + (size_t)kc * ACHP;
        const unsigned char* s1 = aL + (size_t)kc * ACHP;
        const unsigned char* s2 = bH + (size_t)kc * ACHP;
        const unsigned char* s3 = bL + (size_t)kc * ACHP;
        for (int i = tid; i < 1152; i += 256) cpa16(d + i * 16, s0 + i * 16);
        for (int i = tid; i < 1152; i += 256) cpa16(d + 18432 + i * 16, s1 + i * 16);
        for (int i = tid; i < 1152; i += 256) cpa16(d + 36864 + i * 16, s2 + i * 16);
        for (int i = tid; i < 1152; i += 256) cpa16(d + 55296 + i * 16, s3 + i * 16);
        CP_COMMIT();
    };

    float acc[16][4];
#pragma unroll
    for (int n = 0; n < 16; n++)
#pragma unroll
        for (int q = 0; q < 4; q++) acc[n][q] = 0.f;

    issue(0); issue(1);
    for (int kc = 0; kc < 16; kc++) {
        if (kc == 15) CP_WAIT0(); else CP_WAIT1();
        __syncthreads();
        const unsigned char* As = smem + (kc & 1) * FBUFSZ;
        const unsigned char* Al = As + 18432;
        const unsigned char* Bh = As + 36864;
        const unsigned char* Bl = As + 55296;
        const int rb = (16 * w + g) * 144 + tig * 4;
#pragma unroll
        for (int ks = 0; ks < 4; ks++) {
            const int ao = rb + ks * 32;
            uint32_t ah[4], al4[4];
            ah[0] = *(const uint32_t*)(As + ao);
            ah[1] = *(const uint32_t*)(As + ao + 1152);
            ah[2] = *(const uint32_t*)(As + ao + 16);
            ah[3] = *(const uint32_t*)(As + ao + 1168);
            al4[0] = *(const uint32_t*)(Al + ao);
            al4[1] = *(const uint32_t*)(Al + ao + 1152);
            al4[2] = *(const uint32_t*)(Al + ao + 16);
            al4[3] = *(const uint32_t*)(Al + ao + 1168);
#pragma unroll
            for (int nt = 0; nt < 16; nt++) {
                const int bo = (8 * nt + g) * 144 + tig * 4 + ks * 32;
                uint32_t bh0 = *(const uint32_t*)(Bh + bo);
                uint32_t bh1 = *(const uint32_t*)(Bh + bo + 16);
                uint32_t bl0 = *(const uint32_t*)(Bl + bo);
                uint32_t bl1 = *(const uint32_t*)(Bl + bo + 16);
                hmma(acc[nt], ah, bh0, bh1);
                hmma(acc[nt], al4, bh0, bh1);
                hmma(acc[nt], ah, bl0, bl1);
            }
        }
        __syncthreads();
        if (kc + 2 < 16) issue(kc + 2);
    }

#pragma unroll
    for (int nt = 0; nt < 16; nt++) {
        int d = dt * 128 + 8 * nt + 2 * tig;
        float2 bb = *(const float2*)(bfc + d);
        int n0 = 16 * w + g;
        float2 v0 = make_float2(acc[nt][0] + bb.x, acc[nt][1] + bb.y);
        float2 v1 = make_float2(acc[nt][2] + bb.x, acc[nt][3] + bb.y);
        *(float2*)(out + ((size_t)n0 * TT + s) * 1024 + d) = v0;
        *(float2*)(out + ((size_t)(n0 + 8) * TT + s) * 1024 + d) = v1;
    }
}

// ------------------------- launch -------------------------
extern "C" void kernel_launch(void* const* d_in, const int* in_sizes, int n_in,
                              void* d_out, int out_size)
{
    const float* hT  = (const float*)d_in[0];
    const float* Wih = (const float*)d_in[1];
    const float* Whh = (const float*)d_in[2];
    const float* bih = (const float*)d_in[3];
    const float* bhh = (const float*)d_in[4];
    const float* Wfc = (const float*)d_in[5];
    const float* bfc = (const float*)d_in[6];
    float* out = (float*)d_out;

    cudaFuncSetAttribute(lstm_persistent, cudaFuncAttributeMaxDynamicSharedMemorySize, SM_STEP);
    cudaFuncSetAttribute(fc_kernel,       cudaFuncAttributeMaxDynamicSharedMemorySize, SM_FC);

    prep<<<1024, 256>>>(hT, Wih, Whh, bih, bhh, Wfc);
    lstm_persistent<<<NCTA, 256, SM_STEP>>>();
    fc_kernel<<<dim3(TT, 8), 256, SM_FC>>>(bfc, out);
}

// round 6
// speedup vs baseline: 4.1280x; 1.1843x over previous
#include <cuda_runtime.h>
#include <cuda_bf16.h>
#include <cstdint>

#define TT 256
#define NLSTM 128
#define ACHP 18432                 // padded A chunk: 128 rows x 144B
#define SLOTP (16*ACHP)            // per A slot per matrix
#define BCHP 4608                  // padded W chunk: 32 rows x 144B
#define WCTAP (16*BCHP)            // 73728 per CTA per matrix
#define FCDP (16*ACHP)             // FC W d-tile per matrix

// ------------------------- device scratch -------------------------
__device__ __align__(128) unsigned char g_Ahi[(size_t)(TT+1)*SLOTP];
__device__ __align__(128) unsigned char g_Alo[(size_t)(TT+1)*SLOTP];
__device__ __align__(128) unsigned char g_WsHi[(size_t)NLSTM*WCTAP];
__device__ __align__(128) unsigned char g_WsLo[(size_t)NLSTM*WCTAP];
__device__ __align__(128) unsigned char g_W0Hi[(size_t)NLSTM*WCTAP];
__device__ __align__(128) unsigned char g_W0Lo[(size_t)NLSTM*WCTAP];
__device__ __align__(128) unsigned char g_FcHi[(size_t)8*FCDP];
__device__ __align__(128) unsigned char g_FcLo[(size_t)8*FCDP];
__device__ float g_biasP[NLSTM*32];
__device__ unsigned g_bar;
__device__ unsigned g_fcitem;

// ------------------------- helpers -------------------------
__device__ __forceinline__ uint32_t smem_u32(const void* p) {
    uint32_t a;
    asm("{ .reg .u64 t; cvta.to.shared.u64 t, %1; cvt.u32.u64 %0, t; }" : "=r"(a) : "l"(p));
    return a;
}
__device__ __forceinline__ void cpa16(uint32_t dst, const void* src) {
    asm volatile("cp.async.cg.shared.global [%0], [%1], 16;" :: "r"(dst), "l"(src));
}
#define CP_COMMIT() asm volatile("cp.async.commit_group;")
#define CP_WAIT1()  asm volatile("cp.async.wait_group 1;")
#define CP_WAIT0()  asm volatile("cp.async.wait_group 0;")

__device__ __forceinline__ void hmma(float* c, const uint32_t* a, uint32_t b0, uint32_t b1) {
    asm volatile(
        "mma.sync.aligned.m16n8k16.row.col.f32.bf16.bf16.f32 "
        "{%0,%1,%2,%3}, {%4,%5,%6,%7}, {%8,%9}, {%0,%1,%2,%3};"
        : "+f"(c[0]), "+f"(c[1]), "+f"(c[2]), "+f"(c[3])
        : "r"(a[0]), "r"(a[1]), "r"(a[2]), "r"(a[3]), "r"(b0), "r"(b1));
}
__device__ __forceinline__ float sigf(float x)  { return 1.0f / (1.0f + __expf(-x)); }
__device__ __forceinline__ float tanhx(float x) { return 2.0f / (1.0f + __expf(-2.0f * x)) - 1.0f; }

__device__ __forceinline__ void pack8(const float* v, uint4& hi, uint4& lo) {
    __nv_bfloat16 h[8]; float r[8];
#pragma unroll
    for (int e = 0; e < 8; e++) { h[e] = __float2bfloat16(v[e]); r[e] = v[e] - __bfloat162float(h[e]); }
    uint32_t* hw = (uint32_t*)&hi; uint32_t* lw = (uint32_t*)&lo;
#pragma unroll
    for (int q = 0; q < 4; q++) {
        __nv_bfloat162 ph = __halves2bfloat162(h[2*q], h[2*q+1]);
        __nv_bfloat162 pl = __halves2bfloat162(__float2bfloat16(r[2*q]), __float2bfloat16(r[2*q+1]));
        hw[q] = *(uint32_t*)&ph; lw[q] = *(uint32_t*)&pl;
    }
}

// ------------------------- prep -------------------------
__global__ void prep(const float* __restrict__ hT, const float* __restrict__ Wih,
                     const float* __restrict__ Whh, const float* __restrict__ bih,
                     const float* __restrict__ bhh, const float* __restrict__ Wfc)
{
    size_t idx = (size_t)blockIdx.x * blockDim.x + threadIdx.x;
    size_t str = (size_t)gridDim.x * blockDim.x;
    if (idx == 0) { g_bar = 0; g_fcitem = 0; }

    for (size_t i = idx; i < (size_t)524288; i += str) {
        int kg = (int)(i & 127), np = (int)((i >> 7) & 31), cta = (int)(i >> 12);
        int row = (np & 3) * 1024 + cta * 8 + (np >> 2);
        int k = kg * 8;
        float wi[8], ws[8];
#pragma unroll
        for (int e = 0; e < 8; e++) {
            float a = Wih[(size_t)row * 1024 + k + e];
            wi[e] = a; ws[e] = a + Whh[(size_t)row * 1024 + k + e];
        }
        size_t base = (size_t)cta * WCTAP + (size_t)(kg >> 3) * BCHP + np * 144 + (kg & 7) * 16;
        uint4 h4, l4;
        pack8(wi, h4, l4);
        *(uint4*)(g_W0Hi + base) = h4; *(uint4*)(g_W0Lo + base) = l4;
        pack8(ws, h4, l4);
        *(uint4*)(g_WsHi + base) = h4; *(uint4*)(g_WsLo + base) = l4;
    }
    for (size_t i = idx; i < (size_t)131072; i += str) {
        int kg = (int)(i & 127), np = (int)((i >> 7) & 127), dt = (int)(i >> 14);
        float w[8];
#pragma unroll
        for (int e = 0; e < 8; e++) w[e] = Wfc[(size_t)(dt * 128 + np) * 1024 + kg * 8 + e];
        size_t base = (size_t)dt * FCDP + (size_t)(kg >> 3) * ACHP + np * 144 + (kg & 7) * 16;
        uint4 h4, l4;
        pack8(w, h4, l4);
        *(uint4*)(g_FcHi + base) = h4; *(uint4*)(g_FcLo + base) = l4;
    }
    for (size_t i = idx; i < (size_t)16384; i += str) {
        int kg = (int)(i & 127), m = (int)(i >> 7);
        float v[8];
#pragma unroll
        for (int e = 0; e < 8; e++) v[e] = hT[(size_t)m * 1024 + kg * 8 + e];
        size_t base = (size_t)(kg >> 3) * ACHP + m * 144 + (kg & 7) * 16;
        uint4 h4, l4;
        pack8(v, h4, l4);
        *(uint4*)(g_Ahi + base) = h4; *(uint4*)(g_Alo + base) = l4;
    }
    for (size_t i = idx; i < (size_t)4096; i += str) {
        int np = (int)(i & 31), cta = (int)(i >> 5);
        int row = (np & 3) * 1024 + cta * 8 + (np >> 2);
        g_biasP[i] = bih[row] + bhh[row];
    }
}

// ------------------------- fused persistent kernel -------------------------
// LSTM smem: [0,73728) Whi resident | [73728,147456) Wlo resident
//            [147456, 221184) two A buffers x 36864 {Ahi 18432|Alo 18432}
//            [221184) bias 128B, [221312) item slot
// FC smem (after conversion): 2 buffers x 73728 {Ahi|Alo|Bhi|Blo} in [0,147456)
#define W_LO   73728
#define ABUF   147456
#define S_BIAS 221184
#define S_ITEM 221312
#define SM_ALL 221440

__global__ void __launch_bounds__(256, 1) lstm_fused(const float* __restrict__ bfc,
                                                     float* __restrict__ out)
{
    extern __shared__ unsigned char smem[];
    const uint32_t sb = smem_u32(smem);
    const int tid = threadIdx.x;
    const int w = tid >> 5, lane = tid & 31;
    const int g = lane >> 2, tig = lane & 3;
    const int cta = blockIdx.x;

    if (cta < NLSTM) {
        // ---------------- LSTM role ----------------
        if (tid < 32) ((float*)(smem + S_BIAS))[tid] = g_biasP[cta * 32 + tid];
        const float* biasS = (const float*)(smem + S_BIAS);

        // resident W <- W0 (t=0 weights)
        {
            const unsigned char* s2 = g_W0Hi + (size_t)cta * WCTAP;
            const unsigned char* s3 = g_W0Lo + (size_t)cta * WCTAP;
            for (int i = tid; i < 4608; i += 256) cpa16(sb + i * 16, s2 + i * 16);
            for (int i = tid; i < 4608; i += 256) cpa16(sb + W_LO + i * 16, s3 + i * 16);
            CP_COMMIT();
        }

        float c[4] = {0.f, 0.f, 0.f, 0.f};

        for (int t = 0; t < TT; t++) {
            if (tid == 0 && t > 0) {
                unsigned tgt = (unsigned)(NLSTM * t), v;
                do {
                    asm volatile("ld.acquire.gpu.global.u32 %0, [%1];" : "=r"(v) : "l"(&g_bar));
                    if ((int)(v - tgt) >= 0) break;
                    __nanosleep(32);
                } while (1);
            }
            __syncthreads();

            const unsigned char* aH = g_Ahi + (size_t)t * SLOTP;
            const unsigned char* aL = g_Alo + (size_t)t * SLOTP;

            auto issueA = [&](int kc) {
                uint32_t d = sb + ABUF + (kc & 1) * 36864;
                const unsigned char* sA = aH + (size_t)kc * ACHP;
                const unsigned char* sL = aL + (size_t)kc * ACHP;
                for (int i = tid; i < 1152; i += 256) cpa16(d + i * 16, sA + i * 16);
                for (int i = tid; i < 1152; i += 256) cpa16(d + 18432 + i * 16, sL + i * 16);
                CP_COMMIT();
            };

            float acc[4][4];
#pragma unroll
            for (int n = 0; n < 4; n++)
#pragma unroll
                for (int q = 0; q < 4; q++) acc[n][q] = 0.f;

            issueA(0); issueA(1);
            for (int kc = 0; kc < 16; kc++) {
                if (kc == 15) CP_WAIT0(); else CP_WAIT1();
                __syncthreads();
                const unsigned char* As = smem + ABUF + (kc & 1) * 36864;
                const unsigned char* Al = As + 18432;
                const unsigned char* Bh = smem + kc * BCHP;
                const unsigned char* Bl = smem + W_LO + kc * BCHP;
                const int rb = (16 * w + g) * 144 + tig * 4;
#pragma unroll
                for (int ks = 0; ks < 4; ks++) {
                    const int ao = rb + ks * 32;
                    uint32_t ah[4], al4[4];
                    ah[0] = *(const uint32_t*)(As + ao);
                    ah[1] = *(const uint32_t*)(As + ao + 1152);
                    ah[2] = *(const uint32_t*)(As + ao + 16);
                    ah[3] = *(const uint32_t*)(As + ao + 1168);
                    al4[0] = *(const uint32_t*)(Al + ao);
                    al4[1] = *(const uint32_t*)(Al + ao + 1152);
                    al4[2] = *(const uint32_t*)(Al + ao + 16);
                    al4[3] = *(const uint32_t*)(Al + ao + 1168);
#pragma unroll
                    for (int nt = 0; nt < 4; nt++) {
                        const int bo = (8 * nt + g) * 144 + tig * 4 + ks * 32;
                        uint32_t bh0 = *(const uint32_t*)(Bh + bo);
                        uint32_t bh1 = *(const uint32_t*)(Bh + bo + 16);
                        uint32_t bl0 = *(const uint32_t*)(Bl + bo);
                        uint32_t bl1 = *(const uint32_t*)(Bl + bo + 16);
                        hmma(acc[nt], ah, bh0, bh1);
                        hmma(acc[nt], al4, bh0, bh1);
                        hmma(acc[nt], ah, bl0, bl1);
                    }
                }
                __syncthreads();
                if (kc + 2 < 16) issueA(kc + 2);
            }

            if (t == 0) {   // swap resident W -> Wsum (overlaps epilogue+barrier)
                const unsigned char* s2 = g_WsHi + (size_t)cta * WCTAP;
                const unsigned char* s3 = g_WsLo + (size_t)cta * WCTAP;
                for (int i = tid; i < 4608; i += 256) cpa16(sb + i * 16, s2 + i * 16);
                for (int i = tid; i < 4608; i += 256) cpa16(sb + W_LO + i * 16, s3 + i * 16);
                CP_COMMIT();
            }

            // epilogue
            const int parity = lane & 1;
#pragma unroll
            for (int nt = 0; nt < 4; nt++) {
                float d0 = acc[nt][0], d1 = acc[nt][1], d2 = acc[nt][2], d3 = acc[nt][3];
                float s0 = parity ? d0 : d2;
                float s1 = parity ? d1 : d3;
                float r0 = __shfl_xor_sync(0xffffffffu, s0, 1);
                float r1 = __shfl_xor_sync(0xffffffffu, s1, 1);
                float ivr, fvr, gvr, ovr; int m;
                if (!parity) { ivr = d0; fvr = d1; gvr = r0; ovr = r1; m = 16 * w + g; }
                else         { ivr = r0; fvr = r1; gvr = d2; ovr = d3; m = 16 * w + g + 8; }
                int u = 2 * nt + (tig >> 1);
                const float* bb = biasS + 4 * u;
                float iv = sigf(ivr + bb[0]);
                float fv = sigf(fvr + bb[1]);
                float gv = tanhx(gvr + bb[2]);
                float ov = sigf(ovr + bb[3]);
                c[nt] = fv * c[nt] + iv * gv;
                float h = ov * tanhx(c[nt]);
                int j = cta * 8 + u;
                size_t off = (size_t)(t + 1) * SLOTP + (size_t)(j >> 6) * ACHP
                           + (size_t)m * 144 + (j & 63) * 2;
                __nv_bfloat16 hh = __float2bfloat16(h);
                *(__nv_bfloat16*)(g_Ahi + off) = hh;
                *(__nv_bfloat16*)(g_Alo + off) = __float2bfloat16(h - __bfloat162float(hh));
            }
            __syncthreads();
            if (tid == 0)
                asm volatile("red.release.gpu.global.add.u32 [%0], %1;" :: "l"(&g_bar), "r"(1u) : "memory");
        }
        CP_WAIT0();
        __syncthreads();
    }

    // ---------------- FC worker role (all CTAs end up here) ----------------
    unsigned* itemp = (unsigned*)(smem + S_ITEM);
    for (;;) {
        __syncthreads();
        if (tid == 0) *itemp = atomicAdd(&g_fcitem, 1u);
        __syncthreads();
        unsigned item = *itemp;
        if (item >= 2048u) break;
        int s = (int)(item >> 3), dt = (int)(item & 7);

        if (tid == 0) {
            unsigned tgt = (unsigned)(NLSTM * (s + 1)), v;
            do {
                asm volatile("ld.acquire.gpu.global.u32 %0, [%1];" : "=r"(v) : "l"(&g_bar));
                if ((int)(v - tgt) >= 0) break;
                __nanosleep(64);
            } while (1);
        }
        __syncthreads();

        const unsigned char* aH = g_Ahi + (size_t)(s + 1) * SLOTP;
        const unsigned char* aL = g_Alo + (size_t)(s + 1) * SLOTP;
        const unsigned char* bH = g_FcHi + (size_t)dt * FCDP;
        const unsigned char* bL = g_FcLo + (size_t)dt * FCDP;

        auto issueF = [&](int kc) {
            uint32_t d = sb + (kc & 1) * 73728;
            const unsigned char* s0 = aH + (size_t)kc * ACHP;
            const unsigned char* s1 = aL + (size_t)kc * ACHP;
            const unsigned char* s2 = bH + (size_t)kc * ACHP;
            const unsigned char* s3 = bL + (size_t)kc * ACHP;
            for (int i = tid; i < 1152; i += 256) cpa16(d + i * 16, s0 + i * 16);
            for (int i = tid; i < 1152; i += 256) cpa16(d + 18432 + i * 16, s1 + i * 16);
            for (int i = tid; i < 1152; i += 256) cpa16(d + 36864 + i * 16, s2 + i * 16);
            for (int i = tid; i < 1152; i += 256) cpa16(d + 55296 + i * 16, s3 + i * 16);
            CP_COMMIT();
        };

        float acc[16][4];
#pragma unroll
        for (int n = 0; n < 16; n++)
#pragma unroll
            for (int q = 0; q < 4; q++) acc[n][q] = 0.f;

        issueF(0); issueF(1);
        for (int kc = 0; kc < 16; kc++) {
            if (kc == 15) CP_WAIT0(); else CP_WAIT1();
            __syncthreads();
            const unsigned char* As = smem + (kc & 1) * 73728;
            const unsigned char* Al = As + 18432;
            const unsigned char* Bh = As + 36864;
            const unsigned char* Bl = As + 55296;
            const int rb = (16 * w + g) * 144 + tig * 4;
#pragma unroll
            for (int ks = 0; ks < 4; ks++) {
                const int ao = rb + ks * 32;
                uint32_t ah[4], al4[4];
                ah[0] = *(const uint32_t*)(As + ao);
                ah[1] = *(const uint32_t*)(As + ao + 1152);
                ah[2] = *(const uint32_t*)(As + ao + 16);
                ah[3] = *(const uint32_t*)(As + ao + 1168);
                al4[0] = *(const uint32_t*)(Al + ao);
                al4[1] = *(const uint32_t*)(Al + ao + 1152);
                al4[2] = *(const uint32_t*)(Al + ao + 16);
                al4[3] = *(const uint32_t*)(Al + ao + 1168);
#pragma unroll
                for (int nt = 0; nt < 16; nt++) {
                    const int bo = (8 * nt + g) * 144 + tig * 4 + ks * 32;
                    uint32_t bh0 = *(const uint32_t*)(Bh + bo);
                    uint32_t bh1 = *(const uint32_t*)(Bh + bo + 16);
                    uint32_t bl0 = *(const uint32_t*)(Bl + bo);
                    uint32_t bl1 = *(const uint32_t*)(Bl + bo + 16);
                    hmma(acc[nt], ah, bh0, bh1);
                    hmma(acc[nt], al4, bh0, bh1);
                    hmma(acc[nt], ah, bl0, bl1);
                }
            }
            __syncthreads();
            if (kc + 2 < 16) issueF(kc + 2);
        }

#pragma unroll
        for (int nt = 0; nt < 16; nt++) {
            int d = dt * 128 + 8 * nt + 2 * tig;
            float2 bb = *(const float2*)(bfc + d);
            int n0 = 16 * w + g;
            float2 v0 = make_float2(acc[nt][0] + bb.x, acc[nt][1] + bb.y);
            float2 v1 = make_float2(acc[nt][2] + bb.x, acc[nt][3] + bb.y);
            *(float2*)(out + ((size_t)n0 * TT + s) * 1024 + d) = v0;
            *(float2*)(out + ((size_t)(n0 + 8) * TT + s) * 1024 + d) = v1;
        }
    }
}

// ------------------------- launch -------------------------
extern "C" void kernel_launch(void* const* d_in, const int* in_sizes, int n_in,
                              void* d_out, int out_size)
{
    const float* hT  = (const float*)d_in[0];
    const float* Wih = (const float*)d_in[1];
    const float* Whh = (const float*)d_in[2];
    const float* bih = (const float*)d_in[3];
    const float* bhh = (const float*)d_in[4];
    const float* Wfc = (const float*)d_in[5];
    const float* bfc = (const float*)d_in[6];
    float* out = (float*)d_out;

    static int total = 0;
    if (total == 0) {
        int smc = 148;
        if (cudaDeviceGetAttribute(&smc, cudaDevAttrMultiProcessorCount, 0) != cudaSuccess)
            smc = 148;
        total = smc < 129 ? 129 : (smc > 192 ? 192 : smc);
        cudaFuncSetAttribute(lstm_fused, cudaFuncAttributeMaxDynamicSharedMemorySize, SM_ALL);
    }

    prep<<<1024, 256>>>(hT, Wih, Whh, bih, bhh, Wfc);
    lstm_fused<<<total, 256, SM_ALL>>>(bfc, out);
}

// round 8
// speedup vs baseline: 5.0661x; 1.2272x over previous
#include <cuda_runtime.h>
#include <cuda_bf16.h>
#include <cstdint>

#define TT 256
#define NLSTM 128
#define ACHP 18432                 // padded A chunk: 128 rows x 144B
#define SLOTP (16*ACHP)            // per A slot per matrix
#define BCHP 4608                  // padded W chunk: 32 rows x 144B
#define WCTAP (16*BCHP)            // 73728 per CTA per matrix
#define FCDP (16*ACHP)             // FC W d-tile per matrix

// ------------------------- device scratch -------------------------
__device__ __align__(128) unsigned char g_Ahi[(size_t)(TT+1)*SLOTP];
__device__ __align__(128) unsigned char g_Alo[(size_t)(TT+1)*SLOTP];
__device__ __align__(128) unsigned char g_WsHi[(size_t)NLSTM*WCTAP];
__device__ __align__(128) unsigned char g_WsLo[(size_t)NLSTM*WCTAP];
__device__ __align__(128) unsigned char g_W0Hi[(size_t)NLSTM*WCTAP];
__device__ __align__(128) unsigned char g_W0Lo[(size_t)NLSTM*WCTAP];
__device__ __align__(128) unsigned char g_FcHi[(size_t)8*FCDP];
__device__ __align__(128) unsigned char g_FcLo[(size_t)8*FCDP];
__device__ float g_biasP[NLSTM*32];
__device__ unsigned g_bar;
__device__ unsigned g_fcitem;

// ------------------------- helpers -------------------------
__device__ __forceinline__ uint32_t smem_u32(const void* p) {
    uint32_t a;
    asm("{ .reg .u64 t; cvta.to.shared.u64 t, %1; cvt.u32.u64 %0, t; }" : "=r"(a) : "l"(p));
    return a;
}
__device__ __forceinline__ void cpa16(uint32_t dst, const void* src) {
    asm volatile("cp.async.cg.shared.global [%0], [%1], 16;" :: "r"(dst), "l"(src));
}
#define CP_COMMIT() asm volatile("cp.async.commit_group;")
#define CP_WAIT1()  asm volatile("cp.async.wait_group 1;")
#define CP_WAIT0()  asm volatile("cp.async.wait_group 0;")

__device__ __forceinline__ void hmma(float* c, const uint32_t* a, uint32_t b0, uint32_t b1) {
    asm volatile(
        "mma.sync.aligned.m16n8k16.row.col.f32.bf16.bf16.f32 "
        "{%0,%1,%2,%3}, {%4,%5,%6,%7}, {%8,%9}, {%0,%1,%2,%3};"
        : "+f"(c[0]), "+f"(c[1]), "+f"(c[2]), "+f"(c[3])
        : "r"(a[0]), "r"(a[1]), "r"(a[2]), "r"(a[3]), "r"(b0), "r"(b1));
}
__device__ __forceinline__ float sigf(float x)  { return 1.0f / (1.0f + __expf(-x)); }
__device__ __forceinline__ float tanhx(float x) { return 2.0f / (1.0f + __expf(-2.0f * x)) - 1.0f; }

__device__ __forceinline__ void pack8(const float* v, uint4& hi, uint4& lo) {
    __nv_bfloat16 h[8]; float r[8];
#pragma unroll
    for (int e = 0; e < 8; e++) { h[e] = __float2bfloat16(v[e]); r[e] = v[e] - __bfloat162float(h[e]); }
    uint32_t* hw = (uint32_t*)&hi; uint32_t* lw = (uint32_t*)&lo;
#pragma unroll
    for (int q = 0; q < 4; q++) {
        __nv_bfloat162 ph = __halves2bfloat162(h[2*q], h[2*q+1]);
        __nv_bfloat162 pl = __halves2bfloat162(__float2bfloat16(r[2*q]), __float2bfloat16(r[2*q+1]));
        hw[q] = *(uint32_t*)&ph; lw[q] = *(uint32_t*)&pl;
    }
}

// ------------------------- prep -------------------------
__global__ void prep(const float* __restrict__ hT, const float* __restrict__ Wih,
                     const float* __restrict__ Whh, const float* __restrict__ bih,
                     const float* __restrict__ bhh, const float* __restrict__ Wfc)
{
    size_t idx = (size_t)blockIdx.x * blockDim.x + threadIdx.x;
    size_t str = (size_t)gridDim.x * blockDim.x;
    if (idx == 0) { g_bar = 0; g_fcitem = 0; }

    for (size_t i = idx; i < (size_t)524288; i += str) {
        int kg = (int)(i & 127), np = (int)((i >> 7) & 31), cta = (int)(i >> 12);
        int row = (np & 3) * 1024 + cta * 8 + (np >> 2);
        int k = kg * 8;
        float wi[8], ws[8];
#pragma unroll
        for (int e = 0; e < 8; e++) {
            float a = Wih[(size_t)row * 1024 + k + e];
            wi[e] = a; ws[e] = a + Whh[(size_t)row * 1024 + k + e];
        }
        size_t base = (size_t)cta * WCTAP + (size_t)(kg >> 3) * BCHP + np * 144 + (kg & 7) * 16;
        uint4 h4, l4;
        pack8(wi, h4, l4);
        *(uint4*)(g_W0Hi + base) = h4; *(uint4*)(g_W0Lo + base) = l4;
        pack8(ws, h4, l4);
        *(uint4*)(g_WsHi + base) = h4; *(uint4*)(g_WsLo + base) = l4;
    }
    for (size_t i = idx; i < (size_t)131072; i += str) {
        int kg = (int)(i & 127), np = (int)((i >> 7) & 127), dt = (int)(i >> 14);
        float w[8];
#pragma unroll
        for (int e = 0; e < 8; e++) w[e] = Wfc[(size_t)(dt * 128 + np) * 1024 + kg * 8 + e];
        size_t base = (size_t)dt * FCDP + (size_t)(kg >> 3) * ACHP + np * 144 + (kg & 7) * 16;
        uint4 h4, l4;
        pack8(w, h4, l4);
        *(uint4*)(g_FcHi + base) = h4; *(uint4*)(g_FcLo + base) = l4;
    }
    for (size_t i = idx; i < (size_t)16384; i += str) {
        int kg = (int)(i & 127), m = (int)(i >> 7);
        float v[8];
#pragma unroll
        for (int e = 0; e < 8; e++) v[e] = hT[(size_t)m * 1024 + kg * 8 + e];
        size_t base = (size_t)(kg >> 3) * ACHP + m * 144 + (kg & 7) * 16;
        uint4 h4, l4;
        pack8(v, h4, l4);
        *(uint4*)(g_Ahi + base) = h4; *(uint4*)(g_Alo + base) = l4;
    }
    for (size_t i = idx; i < (size_t)4096; i += str) {
        int np = (int)(i & 31), cta = (int)(i >> 5);
        int row = (np & 3) * 1024 + cta * 8 + (np >> 2);
        g_biasP[i] = bih[row] + bhh[row];
    }
}

// ------------------------- fused persistent kernel -------------------------
// LSTM smem: [0,73728) Whi resident | [73728,147456) Wlo resident
//   [147456, 221184) per-warp A staging: 8 warps x { 2 bufs x 4608 {Ahi 2304|Alo 2304} }
//   [221184) bias 128B, [221312) item slot
// FC smem (after conversion): 2 buffers x 73728 {Ahi|Alo|Bhi|Blo} in [0,147456)
#define W_LO   73728
#define ABUF   147456
#define WBUF   9216               // per-warp staging (2 x 4608)
#define S_BIAS 221184
#define S_ITEM 221312
#define SM_ALL 221440

__global__ void __launch_bounds__(256, 1) lstm_fused(const float* __restrict__ bfc,
                                                     float* __restrict__ out)
{
    extern __shared__ unsigned char smem[];
    const uint32_t sb = smem_u32(smem);
    const int tid = threadIdx.x;
    const int w = tid >> 5, lane = tid & 31;
    const int g = lane >> 2, tig = lane & 3;
    const int cta = blockIdx.x;

    if (cta < NLSTM) {
        // ---------------- LSTM role ----------------
        if (tid < 32) ((float*)(smem + S_BIAS))[tid] = g_biasP[cta * 32 + tid];
        const float* biasS = (const float*)(smem + S_BIAS);

        // resident W <- W0
        {
            const unsigned char* s2 = g_W0Hi + (size_t)cta * WCTAP;
            const unsigned char* s3 = g_W0Lo + (size_t)cta * WCTAP;
            for (int i = tid; i < 4608; i += 256) cpa16(sb + i * 16, s2 + i * 16);
            for (int i = tid; i < 4608; i += 256) cpa16(sb + W_LO + i * 16, s3 + i * 16);
            CP_COMMIT();
            CP_WAIT0();
        }

        float c[4] = {0.f, 0.f, 0.f, 0.f};
        const uint32_t mybuf = sb + ABUF + w * WBUF;      // this warp's staging
        const int rowoff = 16 * w;                        // my A rows: 16w..16w+15

        for (int t = 0; t < TT; t++) {
            if (tid == 0 && t > 0) {
                unsigned tgt = (unsigned)(NLSTM * t), v;
                do {
                    asm volatile("ld.acquire.gpu.global.u32 %0, [%1];" : "=r"(v) : "l"(&g_bar));
                    if ((int)(v - tgt) >= 0) break;
                    __nanosleep(32);
                } while (1);
            }
            __syncthreads();

            // my 16 rows of the A slot, hi and lo
            const unsigned char* aH = g_Ahi + (size_t)t * SLOTP + (size_t)rowoff * 144;
            const unsigned char* aL = g_Alo + (size_t)t * SLOTP + (size_t)rowoff * 144;

            // per-warp load of one chunk (16 rows x 144B, hi+lo) into my buffer
            auto issueA = [&](int kc) {
                uint32_t d = mybuf + (kc & 1) * 4608;
                const unsigned char* sA = aH + (size_t)kc * ACHP;
                const unsigned char* sL = aL + (size_t)kc * ACHP;
#pragma unroll
                for (int i = 0; i < 5; i++) {
                    int e = lane + i * 32;                // 144 16B-units hi
                    if (e < 144) cpa16(d + e * 16, sA + e * 16);
                }
#pragma unroll
                for (int i = 0; i < 5; i++) {
                    int e = lane + i * 32;                // 144 16B-units lo
                    if (e < 144) cpa16(d + 2304 + e * 16, sL + e * 16);
                }
                CP_COMMIT();
            };

            float acc[4][4];
#pragma unroll
            for (int n = 0; n < 4; n++)
#pragma unroll
                for (int q = 0; q < 4; q++) acc[n][q] = 0.f;

            issueA(0); issueA(1);
            for (int kc = 0; kc < 16; kc++) {
                if (kc == 15) CP_WAIT0(); else CP_WAIT1();
                __syncwarp();
                const unsigned char* As = smem + ABUF + w * WBUF + (kc & 1) * 4608;
                const unsigned char* Al = As + 2304;
                const unsigned char* Bh = smem + kc * BCHP;
                const unsigned char* Bl = smem + W_LO + kc * BCHP;
                const int rb = g * 144 + tig * 4;         // row g within my 16-row tile
#pragma unroll
                for (int ks = 0; ks < 4; ks++) {
                    const int ao = rb + ks * 32;
                    uint32_t ah[4], al4[4];
                    ah[0] = *(const uint32_t*)(As + ao);
                    ah[1] = *(const uint32_t*)(As + ao + 1152);
                    ah[2] = *(const uint32_t*)(As + ao + 16);
                    ah[3] = *(const uint32_t*)(As + ao + 1168);
                    al4[0] = *(const uint32_t*)(Al + ao);
                    al4[1] = *(const uint32_t*)(Al + ao + 1152);
                    al4[2] = *(const uint32_t*)(Al + ao + 16);
                    al4[3] = *(const uint32_t*)(Al + ao + 1168);
#pragma unroll
                    for (int nt = 0; nt < 4; nt++) {
                        const int bo = (8 * nt + g) * 144 + tig * 4 + ks * 32;
                        uint32_t bh0 = *(const uint32_t*)(Bh + bo);
                        uint32_t bh1 = *(const uint32_t*)(Bh + bo + 16);
                        uint32_t bl0 = *(const uint32_t*)(Bl + bo);
                        uint32_t bl1 = *(const uint32_t*)(Bl + bo + 16);
                        hmma(acc[nt], ah, bh0, bh1);
                        hmma(acc[nt], al4, bh0, bh1);
                        hmma(acc[nt], ah, bl0, bl1);
                    }
                }
                __syncwarp();
                if (kc + 2 < 16) issueA(kc + 2);
            }

            if (t == 0) {
                // RACE FIX: all warps must finish reading W0 before the swap
                // (warps are decoupled in the mainloop; without this barrier a
                // fast warp overwrites W0 while slow warps still compute with it)
                __syncthreads();
                const unsigned char* s2 = g_WsHi + (size_t)cta * WCTAP;
                const unsigned char* s3 = g_WsLo + (size_t)cta * WCTAP;
                for (int i = tid; i < 4608; i += 256) cpa16(sb + i * 16, s2 + i * 16);
                for (int i = tid; i < 4608; i += 256) cpa16(sb + W_LO + i * 16, s3 + i * 16);
                CP_COMMIT();
                CP_WAIT0();
            }

            // epilogue
            const int parity = lane & 1;
#pragma unroll
            for (int nt = 0; nt < 4; nt++) {
                float d0 = acc[nt][0], d1 = acc[nt][1], d2 = acc[nt][2], d3 = acc[nt][3];
                float s0 = parity ? d0 : d2;
                float s1 = parity ? d1 : d3;
                float r0 = __shfl_xor_sync(0xffffffffu, s0, 1);
                float r1 = __shfl_xor_sync(0xffffffffu, s1, 1);
                float ivr, fvr, gvr, ovr; int m;
                if (!parity) { ivr = d0; fvr = d1; gvr = r0; ovr = r1; m = 16 * w + g; }
                else         { ivr = r0; fvr = r1; gvr = d2; ovr = d3; m = 16 * w + g + 8; }
                int u = 2 * nt + (tig >> 1);
                const float* bb = biasS + 4 * u;
                float iv = sigf(ivr + bb[0]);
                float fv = sigf(fvr + bb[1]);
                float gv = tanhx(gvr + bb[2]);
                float ov = sigf(ovr + bb[3]);
                c[nt] = fv * c[nt] + iv * gv;
                float h = ov * tanhx(c[nt]);
                int j = cta * 8 + u;
                size_t off = (size_t)(t + 1) * SLOTP + (size_t)(j >> 6) * ACHP
                           + (size_t)m * 144 + (j & 63) * 2;
                __nv_bfloat16 hh = __float2bfloat16(h);
                *(__nv_bfloat16*)(g_Ahi + off) = hh;
                *(__nv_bfloat16*)(g_Alo + off) = __float2bfloat16(h - __bfloat162float(hh));
            }
            __syncthreads();
            if (tid == 0)
                asm volatile("red.release.gpu.global.add.u32 [%0], %1;" :: "l"(&g_bar), "r"(1u) : "memory");
        }
        __syncthreads();
    }

    // ---------------- FC worker role (all CTAs end up here) ----------------
    unsigned* itemp = (unsigned*)(smem + S_ITEM);
    for (;;) {
        __syncthreads();
        if (tid == 0) *itemp = atomicAdd(&g_fcitem, 1u);
        __syncthreads();
        unsigned item = *itemp;
        if (item >= 2048u) break;
        int s = (int)(item >> 3), dt = (int)(item & 7);

        if (tid == 0) {
            unsigned tgt = (unsigned)(NLSTM * (s + 1)), v;
            do {
                asm volatile("ld.acquire.gpu.global.u32 %0, [%1];" : "=r"(v) : "l"(&g_bar));
                if ((int)(v - tgt) >= 0) break;
                __nanosleep(64);
            } while (1);
        }
        __syncthreads();

        const unsigned char* aH = g_Ahi + (size_t)(s + 1) * SLOTP;
        const unsigned char* aL = g_Alo + (size_t)(s + 1) * SLOTP;
        const unsigned char* bH = g_FcHi + (size_t)dt * FCDP;
        const unsigned char* bL = g_FcLo + (size_t)dt * FCDP;

        auto issueF = [&](int kc) {
            uint32_t d = sb + (kc & 1) * 73728;
            const unsigned char* s0 = aH + (size_t)kc * ACHP;
            const unsigned char* s1 = aL + (size_t)kc * ACHP;
            const unsigned char* s2 = bH + (size_t)kc * ACHP;
            const unsigned char* s3 = bL + (size_t)kc * ACHP;
            for (int i = tid; i < 1152; i += 256) cpa16(d + i * 16, s0 + i * 16);
            for (int i = tid; i < 1152; i += 256) cpa16(d + 18432 + i * 16, s1 + i * 16);
            for (int i = tid; i < 1152; i += 256) cpa16(d + 36864 + i * 16, s2 + i * 16);
            for (int i = tid; i < 1152; i += 256) cpa16(d + 55296 + i * 16, s3 + i * 16);
            CP_COMMIT();
        };

        float acc[16][4];
#pragma unroll
        for (int n = 0; n < 16; n++)
#pragma unroll
            for (int q = 0; q < 4; q++) acc[n][q] = 0.f;

        issueF(0); issueF(1);
        for (int kc = 0; kc < 16; kc++) {
            if (kc == 15) CP_WAIT0(); else CP_WAIT1();
            __syncthreads();
            const unsigned char* As = smem + (kc & 1) * 73728;
            const unsigned char* Al = As + 18432;
            const unsigned char* Bh = As + 36864;
            const unsigned char* Bl = As + 55296;
            const int rb = (16 * w + g) * 144 + tig * 4;
#pragma unroll
            for (int ks = 0; ks < 4; ks++) {
                const int ao = rb + ks * 32;
                uint32_t ah[4], al4[4];
                ah[0] = *(const uint32_t*)(As + ao);
                ah[1] = *(const uint32_t*)(As + ao + 1152);
                ah[2] = *(const uint32_t*)(As + ao + 16);
                ah[3] = *(const uint32_t*)(As + ao + 1168);
                al4[0] = *(const uint32_t*)(Al + ao);
                al4[1] = *(const uint32_t*)(Al + ao + 1152);
                al4[2] = *(const uint32_t*)(Al + ao + 16);
                al4[3] = *(const uint32_t*)(Al + ao + 1168);
#pragma unroll
                for (int nt = 0; nt < 16; nt++) {
                    const int bo = (8 * nt + g) * 144 + tig * 4 + ks * 32;
                    uint32_t bh0 = *(const uint32_t*)(Bh + bo);
                    uint32_t bh1 = *(const uint32_t*)(Bh + bo + 16);
                    uint32_t bl0 = *(const uint32_t*)(Bl + bo);
                    uint32_t bl1 = *(const uint32_t*)(Bl + bo + 16);
                    hmma(acc[nt], ah, bh0, bh1);
                    hmma(acc[nt], al4, bh0, bh1);
                    hmma(acc[nt], ah, bl0, bl1);
                }
            }
            __syncthreads();
            if (kc + 2 < 16) issueF(kc + 2);
        }

#pragma unroll
        for (int nt = 0; nt < 16; nt++) {
            int d = dt * 128 + 8 * nt + 2 * tig;
            float2 bb = *(const float2*)(bfc + d);
            int n0 = 16 * w + g;
            float2 v0 = make_float2(acc[nt][0] + bb.x, acc[nt][1] + bb.y);
            float2 v1 = make_float2(acc[nt][2] + bb.x, acc[nt][3] + bb.y);
            *(float2*)(out + ((size_t)n0 * TT + s) * 1024 + d) = v0;
            *(float2*)(out + ((size_t)(n0 + 8) * TT + s) * 1024 + d) = v1;
        }
    }
}

// ------------------------- launch -------------------------
extern "C" void kernel_launch(void* const* d_in, const int* in_sizes, int n_in,
                              void* d_out, int out_size)
{
    const float* hT  = (const float*)d_in[0];
    const float* Wih = (const float*)d_in[1];
    const float* Whh = (const float*)d_in[2];
    const float* bih = (const float*)d_in[3];
    const float* bhh = (const float*)d_in[4];
    const float* Wfc = (const float*)d_in[5];
    const float* bfc = (const float*)d_in[6];
    float* out = (float*)d_out;

    static int total = 0;
    if (total == 0) {
        int smc = 148;
        if (cudaDeviceGetAttribute(&smc, cudaDevAttrMultiProcessorCount, 0) != cudaSuccess)
            smc = 148;
        total = smc < 129 ? 129 : (smc > 192 ? 192 : smc);
        cudaFuncSetAttribute(lstm_fused, cudaFuncAttributeMaxDynamicSharedMemorySize, SM_ALL);
    }

    prep<<<1024, 256>>>(hT, Wih, Whh, bih, bhh, Wfc);
    lstm_fused<<<total, 256, SM_ALL>>>(bfc, out);
}